// round 13
// baseline (speedup 1.0000x reference)
#include <cuda_runtime.h>
#include <cuda_fp16.h>
#include <cstdint>

#define NSEQ   2048
#define DMODEL 1024
#define HEADS  16
#define DH     64
#define CTX    128
#define QT     256
#define NTHR   512
#define NCHUNK 8
#define SP     72            // padded smem row stride (fp16 elems) -> 144B
#define QSCALE 0.18033688011112042f   // 0.125 * log2(e): softmax = 2^s
#define KVTILE (64*SP*2)     // 9216 B per 64x64 fp16 tile

// ---- smem byte offsets ----
#define QTI  0                        // 256xSP fp16 = 36864
#define KT0  36864
#define KT1  (KT0 + KVTILE)
#define VT0  (KT1 + KVTILE)
#define VT1  (VT0 + KVTILE)
#define RAWK (VT1 + KVTILE)          // fp32 staging 64x64
#define RAWV (RAWK + 16384)
#define SMEM_BYTES (RAWV + 16384)    // 106496
// epilogue alias (over K/V tiles + raw, AFTER a full __syncthreads): 256x68 f32
#define OB   KT0
#define OPS  68

__device__ __forceinline__ uint32_t smem_u32(const void* p) {
    uint32_t a;
    asm("{ .reg .u64 t; cvta.to.shared.u64 t, %1; cvt.u32.u64 %0, t; }" : "=r"(a) : "l"(p));
    return a;
}
__device__ __forceinline__ void cpa16(uint32_t dst, const void* src) {
    asm volatile("cp.async.cg.shared.global [%0], [%1], 16;" :: "r"(dst), "l"(src));
}
#define CPA_COMMIT() asm volatile("cp.async.commit_group;" ::: "memory")
#define CPA_WAIT0()  asm volatile("cp.async.wait_group 0;" ::: "memory")

__device__ __forceinline__ void ldsm4(uint32_t* r, uint32_t a) {
    asm volatile("ldmatrix.sync.aligned.m8n8.x4.shared.b16 {%0,%1,%2,%3}, [%4];"
                 : "=r"(r[0]), "=r"(r[1]), "=r"(r[2]), "=r"(r[3]) : "r"(a));
}
__device__ __forceinline__ void ldsm4t(uint32_t* r, uint32_t a) {
    asm volatile("ldmatrix.sync.aligned.m8n8.x4.trans.shared.b16 {%0,%1,%2,%3}, [%4];"
                 : "=r"(r[0]), "=r"(r[1]), "=r"(r[2]), "=r"(r[3]) : "r"(a));
}
__device__ __forceinline__ void mma16816(float* c, const uint32_t* a, const uint32_t* b) {
    asm volatile("mma.sync.aligned.m16n8k16.row.col.f32.f16.f16.f32 "
                 "{%0,%1,%2,%3}, {%4,%5,%6,%7}, {%8,%9}, {%0,%1,%2,%3};"
                 : "+f"(c[0]), "+f"(c[1]), "+f"(c[2]), "+f"(c[3])
                 : "r"(a[0]), "r"(a[1]), "r"(a[2]), "r"(a[3]), "r"(b[0]), "r"(b[1]));
}
// pack two fp32 -> fp16x2 (first arg lands in low half)
__device__ __forceinline__ uint32_t pack_f16(float lo, float hi) {
    uint32_t r;
    asm("cvt.rn.f16x2.f32 %0, %1, %2;" : "=r"(r) : "f"(hi), "f"(lo));
    return r;
}
// 2^x on the MUFU pipe
__device__ __forceinline__ float ex2a(float x) {
    float r; asm("ex2.approx.f32 %0, %1;" : "=f"(r) : "f"(x));
    return r;
}

__global__ void __launch_bounds__(NTHR, 1)
sparse_attn_mma(const float* __restrict__ qg, const float* __restrict__ kg,
                const float* __restrict__ vg, float* __restrict__ og)
{
    extern __shared__ char smem[];
    const uint32_t sb = smem_u32(smem);
    const int t    = threadIdx.x;
    const int lane = t & 31, wid = t >> 5;
    const int wr   = wid;              // row group: 16 rows, warp owns all 64 chunk cols
    const int g    = lane >> 2;        // row-in-group (and +8)
    const int qa   = lane & 3;         // col pair selector
    const int h    = blockIdx.y;
    const int i0   = blockIdx.x * QT;
    const size_t hoff = (size_t)h * DH;

    // staging coords: each thread cp.asyncs AND converts exactly its own bytes
    // -> convert needs only wait_group 0 + the per-chunk barrier.
    const int pr  = t >> 4;            // 0..31; +32 per pass, 2 passes -> 64 rows
    const int pc4 = (t & 15) * 4;

    // contiguous valid chunk range: jc in [0, NSEQ-64]
    const int chlo = (i0 >= CTX) ? 0 : (CTX - i0 + 63) / 64;
    const int chhi = min(NCHUNK - 1, (NSEQ - 64 - i0 + CTX) / 64);

    // ---- prologue: prefetch first chunk ----
    {
        const int jc = i0 - CTX + chlo * 64;
        #pragma unroll
        for (int it = 0; it < 2; it++) {
            int r = pr + it * 32;
            cpa16(sb + RAWK + (uint32_t)(r * 64 + pc4) * 4,
                  &kg[(size_t)(jc + r) * DMODEL + hoff + pc4]);
            cpa16(sb + RAWV + (uint32_t)(r * 64 + pc4) * 4,
                  &vg[(size_t)(jc + r) * DMODEL + hoff + pc4]);
        }
        CPA_COMMIT();
    }

    // ---- load Q once: scale (incl. log2e), single fp16 ----
    for (int idx = t; idx < QT * 16; idx += NTHR) {
        int r = idx >> 4, c4 = (idx & 15) * 4;
        float4 q4 = *(const float4*)&qg[(size_t)(i0 + r) * DMODEL + hoff + c4];
        q4.x *= QSCALE; q4.y *= QSCALE; q4.z *= QSCALE; q4.w *= QSCALE;
        uint32_t boff = (uint32_t)(r * SP + c4) * 2;
        *(uint2*)(smem + QTI + boff) = make_uint2(pack_f16(q4.x, q4.y), pack_f16(q4.z, q4.w));
    }

    // ---- prologue convert: raw -> fp16 tiles (own bytes only) ----
    {
        CPA_WAIT0();
        const uint32_t kt = KT0 + (uint32_t)(chlo & 1) * KVTILE;
        const uint32_t vt = VT0 + (uint32_t)(chlo & 1) * KVTILE;
        #pragma unroll
        for (int it = 0; it < 2; it++) {
            int r = pr + it * 32;
            uint32_t roff = (uint32_t)(r * 64 + pc4) * 4;
            uint32_t boff = (uint32_t)(r * SP + pc4) * 2;
            float4 k4 = *(const float4*)(smem + RAWK + roff);
            *(uint2*)(smem + kt + boff) = make_uint2(pack_f16(k4.x, k4.y), pack_f16(k4.z, k4.w));
            float4 v4 = *(const float4*)(smem + RAWV + roff);
            *(uint2*)(smem + vt + boff) = make_uint2(pack_f16(v4.x, v4.y), pack_f16(v4.z, v4.w));
        }
    }
    __syncthreads();   // Q tile + first converts visible

    // ldmatrix per-lane byte offsets
    const int l = lane;
    const uint32_t aoffA = (uint32_t)(((wr * 16 + (l & 15)) * SP + (l >> 4) * 8) * 2);
    const uint32_t aoffB = (uint32_t)((((l & 7) + ((l >> 4) & 1) * 8) * SP
                                      + ((l >> 3) & 1) * 8) * 2);
    const uint32_t aoffV = (uint32_t)((((l & 7) + ((l >> 3) & 1) * 8) * SP
                                      + ((l >> 4) & 1) * 8) * 2);

    // ---- hoist Q fragments into registers (chunk-invariant) ----
    uint32_t aq[4][4];
    #pragma unroll
    for (int k = 0; k < 4; k++)
        ldsm4(aq[k], sb + QTI + aoffA + k * 32);

    float oacc[8][4];
    #pragma unroll
    for (int i = 0; i < 8; i++)
        #pragma unroll
        for (int j = 0; j < 4; j++) oacc[i][j] = 0.f;
    float l0 = 0.f, l1 = 0.f;

    const int ig0 = i0 + wr * 16 + g, ig1 = ig0 + 8;

    for (int ch = chlo; ch <= chhi; ch++) {
        const int b  = ch & 1;
        const int jc = i0 - CTX + ch * 64;

        // ---- prefetch chunk ch+1 (overlaps compute) ----
        if (ch < chhi) {
            const int jn = jc + 64;
            #pragma unroll
            for (int it = 0; it < 2; it++) {
                int r = pr + it * 32;
                cpa16(sb + RAWK + (uint32_t)(r * 64 + pc4) * 4,
                      &kg[(size_t)(jn + r) * DMODEL + hoff + pc4]);
                cpa16(sb + RAWV + (uint32_t)(r * 64 + pc4) * 4,
                      &vg[(size_t)(jn + r) * DMODEL + hoff + pc4]);
            }
            CPA_COMMIT();
        }

        // ---- warp-tile band intersection: keys [jc,jc+64) vs rows [wr*16, wr*16+16) ----
        const int doff = jc - i0;
        const bool active = (doff + 63 >= wr * 16 - CTX) && (doff <= wr * 16 + 15 + CTX);
        if (active) {
            const uint32_t ktb = sb + KT0 + (uint32_t)b * KVTILE;
            const uint32_t vtb = sb + VT0 + (uint32_t)b * KVTILE;

            // ---- GEMM1: S(16x64) = Q K^T (single fp16, Q frags hoisted) ----
            float sacc[8][4];
            #pragma unroll
            for (int i = 0; i < 8; i++)
                #pragma unroll
                for (int j = 0; j < 4; j++) sacc[i][j] = 0.f;

            #pragma unroll
            for (int k = 0; k < 4; k++) {
                #pragma unroll
                for (int nt2 = 0; nt2 < 4; nt2++) {
                    uint32_t bh[4];
                    ldsm4(bh, ktb + aoffB + nt2 * (16 * SP * 2) + k * 32);
                    mma16816(sacc[2 * nt2],     aq[k], bh);
                    mma16816(sacc[2 * nt2 + 1], aq[k], bh + 2);
                }
            }

            // ---- softmax: p = 2^s; mask only tiles straddling the band edge ----
            uint32_t pah[4][4];
            const bool fullband = (doff >= wr * 16 - 113) && (doff <= wr * 16 + 65);
            if (!fullband) {
                #pragma unroll
                for (int nt = 0; nt < 8; nt++) {
                    int jg0 = jc + nt * 8 + 2 * qa, jg1 = jg0 + 1;
                    float p00 = ((unsigned)(jg0 - (ig0 - CTX)) <= 2u * CTX) ? ex2a(sacc[nt][0]) : 0.f;
                    float p01 = ((unsigned)(jg1 - (ig0 - CTX)) <= 2u * CTX) ? ex2a(sacc[nt][1]) : 0.f;
                    float p10 = ((unsigned)(jg0 - (ig1 - CTX)) <= 2u * CTX) ? ex2a(sacc[nt][2]) : 0.f;
                    float p11 = ((unsigned)(jg1 - (ig1 - CTX)) <= 2u * CTX) ? ex2a(sacc[nt][3]) : 0.f;
                    l0 += p00 + p01; l1 += p10 + p11;
                    pah[nt >> 1][(nt & 1) * 2 + 0] = pack_f16(p00, p01);
                    pah[nt >> 1][(nt & 1) * 2 + 1] = pack_f16(p10, p11);
                }
            } else {
                #pragma unroll
                for (int nt = 0; nt < 8; nt++) {
                    float p00 = ex2a(sacc[nt][0]);
                    float p01 = ex2a(sacc[nt][1]);
                    float p10 = ex2a(sacc[nt][2]);
                    float p11 = ex2a(sacc[nt][3]);
                    l0 += p00 + p01; l1 += p10 + p11;
                    pah[nt >> 1][(nt & 1) * 2 + 0] = pack_f16(p00, p01);
                    pah[nt >> 1][(nt & 1) * 2 + 1] = pack_f16(p10, p11);
                }
            }

            // ---- GEMM2: O(16x64) += P V ----
            #pragma unroll
            for (int ks = 0; ks < 4; ks++) {
                #pragma unroll
                for (int nt2 = 0; nt2 < 4; nt2++) {
                    uint32_t vh[4];
                    ldsm4t(vh, vtb + aoffV + ks * (16 * SP * 2) + nt2 * 32);
                    mma16816(oacc[2 * nt2],     pah[ks], vh);
                    mma16816(oacc[2 * nt2 + 1], pah[ks], vh + 2);
                }
            }
        }

        // ---- convert next chunk raw -> tiles(b^1) (own bytes; self-visible) ----
        if (ch < chhi) {
            CPA_WAIT0();
            const uint32_t kt = KT0 + (uint32_t)(b ^ 1) * KVTILE;
            const uint32_t vt = VT0 + (uint32_t)(b ^ 1) * KVTILE;
            #pragma unroll
            for (int it = 0; it < 2; it++) {
                int r = pr + it * 32;
                uint32_t roff = (uint32_t)(r * 64 + pc4) * 4;
                uint32_t boff = (uint32_t)(r * SP + pc4) * 2;
                float4 k4 = *(const float4*)(smem + RAWK + roff);
                *(uint2*)(smem + kt + boff) = make_uint2(pack_f16(k4.x, k4.y),
                                                         pack_f16(k4.z, k4.w));
                float4 v4 = *(const float4*)(smem + RAWV + roff);
                *(uint2*)(smem + vt + boff) = make_uint2(pack_f16(v4.x, v4.y),
                                                         pack_f16(v4.z, v4.w));
            }
        }
        __syncthreads();   // converts visible; tile(b) reads done before overwrite
    }

    // ---- epilogue: in-warp row sums, normalize in regs ----
    l0 += __shfl_xor_sync(0xffffffffu, l0, 1);
    l0 += __shfl_xor_sync(0xffffffffu, l0, 2);
    l1 += __shfl_xor_sync(0xffffffffu, l1, 1);
    l1 += __shfl_xor_sync(0xffffffffu, l1, 2);
    const float inv0 = 1.0f / l0, inv1 = 1.0f / l1;

    __syncthreads();   // all warps done with K/V tiles before aliasing as OB

    float* Ob = (float*)(smem + OB);
    const int r0 = wr * 16 + g, r1 = r0 + 8;
    #pragma unroll
    for (int nt = 0; nt < 8; nt++) {
        int c = nt * 8 + 2 * qa;
        *(float2*)&Ob[r0 * OPS + c] = make_float2(oacc[nt][0] * inv0, oacc[nt][1] * inv0);
        *(float2*)&Ob[r1 * OPS + c] = make_float2(oacc[nt][2] * inv1, oacc[nt][3] * inv1);
    }
    __syncthreads();

    // ---- coalesced store ----
    for (int idx = t; idx < QT * 16; idx += NTHR) {
        int r = idx >> 4, c4 = (idx & 15) * 4;
        float4 o4 = *(const float4*)&Ob[r * OPS + c4];
        *(float4*)&og[(size_t)(i0 + r) * DMODEL + hoff + c4] = o4;
    }
}

extern "C" void kernel_launch(void* const* d_in, const int* in_sizes, int n_in,
                              void* d_out, int out_size) {
    (void)in_sizes; (void)n_in; (void)out_size;
    const float* q = (const float*)d_in[0];
    const float* k = (const float*)d_in[1];
    const float* v = (const float*)d_in[2];
    float* o = (float*)d_out;

    cudaFuncSetAttribute(sparse_attn_mma,
                         cudaFuncAttributeMaxDynamicSharedMemorySize, SMEM_BYTES);
    dim3 grid(NSEQ / QT, HEADS);
    sparse_attn_mma<<<grid, NTHR, SMEM_BYTES>>>(q, k, v, o);
}

// round 14
// speedup vs baseline: 1.0930x; 1.0930x over previous
#include <cuda_runtime.h>
#include <cuda_fp16.h>
#include <cstdint>

#define NSEQ   2048
#define DMODEL 1024
#define HEADS  16
#define DH     64
#define CTX    128
#define QT     128
#define NCHUNK 6
#define SP     72            // padded smem row stride (fp16 elems) -> 144B
#define QSCALE 0.18033688011112042f   // 0.125 * log2(e): softmax = 2^s
#define SSHIFT 4.0f          // p = 2^(s-4); uniform 2^-4 cancels in normalization
#define KVTILE (64*SP*2)     // 9216 B per 64x64 fp16 tile

// ---- smem byte offsets ----
#define QTI  0                        // 128xSP fp16 = 18432
#define KT0  18432
#define KT1  (KT0 + KVTILE)
#define VT0  (KT1 + KVTILE)
#define VT1  (VT0 + KVTILE)
#define RAWK (VT1 + KVTILE)          // fp32 staging 64x64
#define RAWV (RAWK + 16384)
#define SMEM_BYTES (RAWV + 16384)
// epilogue alias (over K/V tiles, AFTER a full __syncthreads): 128x68 f32
#define OB   KT0
#define OPS  68

__device__ __forceinline__ uint32_t smem_u32(const void* p) {
    uint32_t a;
    asm("{ .reg .u64 t; cvta.to.shared.u64 t, %1; cvt.u32.u64 %0, t; }" : "=r"(a) : "l"(p));
    return a;
}
__device__ __forceinline__ void cpa16(uint32_t dst, const void* src) {
    asm volatile("cp.async.cg.shared.global [%0], [%1], 16;" :: "r"(dst), "l"(src));
}
#define CPA_COMMIT() asm volatile("cp.async.commit_group;" ::: "memory")
#define CPA_WAIT0()  asm volatile("cp.async.wait_group 0;" ::: "memory")

__device__ __forceinline__ void ldsm4(uint32_t* r, uint32_t a) {
    asm volatile("ldmatrix.sync.aligned.m8n8.x4.shared.b16 {%0,%1,%2,%3}, [%4];"
                 : "=r"(r[0]), "=r"(r[1]), "=r"(r[2]), "=r"(r[3]) : "r"(a));
}
__device__ __forceinline__ void ldsm4t(uint32_t* r, uint32_t a) {
    asm volatile("ldmatrix.sync.aligned.m8n8.x4.trans.shared.b16 {%0,%1,%2,%3}, [%4];"
                 : "=r"(r[0]), "=r"(r[1]), "=r"(r[2]), "=r"(r[3]) : "r"(a));
}
__device__ __forceinline__ void mma16816(float* c, const uint32_t* a, const uint32_t* b) {
    asm volatile("mma.sync.aligned.m16n8k16.row.col.f32.f16.f16.f32 "
                 "{%0,%1,%2,%3}, {%4,%5,%6,%7}, {%8,%9}, {%0,%1,%2,%3};"
                 : "+f"(c[0]), "+f"(c[1]), "+f"(c[2]), "+f"(c[3])
                 : "r"(a[0]), "r"(a[1]), "r"(a[2]), "r"(a[3]), "r"(b[0]), "r"(b[1]));
}
// pack two fp32 -> fp16x2 (first arg lands in low half)
__device__ __forceinline__ uint32_t pack_f16(float lo, float hi) {
    uint32_t r;
    asm("cvt.rn.f16x2.f32 %0, %1, %2;" : "=r"(r) : "f"(hi), "f"(lo));
    return r;
}
// packed 2^x on the MUFU pipe (fp16x2 in/out)
__device__ __forceinline__ uint32_t ex2_f16x2(uint32_t x) {
    uint32_t r; asm("ex2.approx.f16x2 %0, %1;" : "=r"(r) : "r"(x));
    return r;
}

__global__ void __launch_bounds__(256, 2)
sparse_attn_mma(const float* __restrict__ qg, const float* __restrict__ kg,
                const float* __restrict__ vg, float* __restrict__ og)
{
    extern __shared__ char smem[];
    const uint32_t sb = smem_u32(smem);
    const int t    = threadIdx.x;
    const int lane = t & 31, wid = t >> 5;
    const int wr   = wid;              // row group: 16 rows, warp owns all 64 chunk cols
    const int g    = lane >> 2;        // row-in-group (and +8)
    const int qa   = lane & 3;         // col pair selector
    const int h    = blockIdx.y;
    const int i0   = blockIdx.x * QT;
    const size_t hoff = (size_t)h * DH;

    // staging coords: each thread cp.asyncs AND converts exactly its own bytes
    const int pr  = t >> 4;            // +16 per pass, 4 passes -> 64 rows
    const int pc4 = (t & 15) * 4;

    // contiguous valid chunk range: jc in [0, NSEQ-64]
    const int chlo = (i0 >= CTX) ? 0 : (CTX - i0 + 63) / 64;
    const int chhi = min(NCHUNK - 1, (NSEQ - 64 - i0 + CTX) / 64);

    // ---- prologue: prefetch first chunk ----
    {
        const int jc = i0 - CTX + chlo * 64;
        #pragma unroll
        for (int it = 0; it < 4; it++) {
            int r = pr + it * 16;
            cpa16(sb + RAWK + (uint32_t)(r * 64 + pc4) * 4,
                  &kg[(size_t)(jc + r) * DMODEL + hoff + pc4]);
            cpa16(sb + RAWV + (uint32_t)(r * 64 + pc4) * 4,
                  &vg[(size_t)(jc + r) * DMODEL + hoff + pc4]);
        }
        CPA_COMMIT();
    }

    // ---- load Q once: scale (incl. log2e), single fp16 ----
    for (int idx = t; idx < QT * 16; idx += 256) {
        int r = idx >> 4, c4 = (idx & 15) * 4;
        float4 q4 = *(const float4*)&qg[(size_t)(i0 + r) * DMODEL + hoff + c4];
        q4.x *= QSCALE; q4.y *= QSCALE; q4.z *= QSCALE; q4.w *= QSCALE;
        uint32_t boff = (uint32_t)(r * SP + c4) * 2;
        *(uint2*)(smem + QTI + boff) = make_uint2(pack_f16(q4.x, q4.y), pack_f16(q4.z, q4.w));
    }

    // ---- prologue convert: raw -> fp16 tiles (own bytes only) ----
    {
        CPA_WAIT0();
        const uint32_t kt = KT0 + (uint32_t)(chlo & 1) * KVTILE;
        const uint32_t vt = VT0 + (uint32_t)(chlo & 1) * KVTILE;
        #pragma unroll
        for (int it = 0; it < 4; it++) {
            int r = pr + it * 16;
            uint32_t roff = (uint32_t)(r * 64 + pc4) * 4;
            uint32_t boff = (uint32_t)(r * SP + pc4) * 2;
            float4 k4 = *(const float4*)(smem + RAWK + roff);
            *(uint2*)(smem + kt + boff) = make_uint2(pack_f16(k4.x, k4.y), pack_f16(k4.z, k4.w));
            float4 v4 = *(const float4*)(smem + RAWV + roff);
            *(uint2*)(smem + vt + boff) = make_uint2(pack_f16(v4.x, v4.y), pack_f16(v4.z, v4.w));
        }
    }
    __syncthreads();   // Q tile + first converts visible

    // ldmatrix per-lane byte offsets
    const int l = lane;
    const uint32_t aoffA = (uint32_t)(((wr * 16 + (l & 15)) * SP + (l >> 4) * 8) * 2);
    const uint32_t aoffB = (uint32_t)((((l & 7) + ((l >> 4) & 1) * 8) * SP
                                      + ((l >> 3) & 1) * 8) * 2);
    const uint32_t aoffV = (uint32_t)((((l & 7) + ((l >> 3) & 1) * 8) * SP
                                      + ((l >> 4) & 1) * 8) * 2);

    // ---- hoist Q fragments into registers (chunk-invariant) ----
    uint32_t aq[4][4];
    #pragma unroll
    for (int k = 0; k < 4; k++)
        ldsm4(aq[k], sb + QTI + aoffA + k * 32);

    float oacc[8][4];
    #pragma unroll
    for (int i = 0; i < 8; i++)
        #pragma unroll
        for (int j = 0; j < 4; j++) oacc[i][j] = 0.f;
    float lacc[4] = {0.f, 0.f, 0.f, 0.f};   // row sums via ones-MMA
    const uint32_t ones2[2] = {0x3C003C00u, 0x3C003C00u};  // fp16 1.0 x2

    const int ig0 = i0 + wr * 16 + g, ig1 = ig0 + 8;

    for (int ch = chlo; ch <= chhi; ch++) {
        const int b  = ch & 1;
        const int jc = i0 - CTX + ch * 64;

        // ---- prefetch chunk ch+1 (overlaps compute) ----
        if (ch < chhi) {
            const int jn = jc + 64;
            #pragma unroll
            for (int it = 0; it < 4; it++) {
                int r = pr + it * 16;
                cpa16(sb + RAWK + (uint32_t)(r * 64 + pc4) * 4,
                      &kg[(size_t)(jn + r) * DMODEL + hoff + pc4]);
                cpa16(sb + RAWV + (uint32_t)(r * 64 + pc4) * 4,
                      &vg[(size_t)(jn + r) * DMODEL + hoff + pc4]);
            }
            CPA_COMMIT();
        }

        // ---- warp-tile band intersection: keys [jc,jc+64) vs rows [wr*16, wr*16+16) ----
        const int doff = jc - i0;
        const bool active = (doff + 63 >= wr * 16 - CTX) && (doff <= wr * 16 + 15 + CTX);
        if (active) {
            const uint32_t ktb = sb + KT0 + (uint32_t)b * KVTILE;
            const uint32_t vtb = sb + VT0 + (uint32_t)b * KVTILE;

            // ---- GEMM1: S(16x64) = Q K^T (single fp16, Q frags hoisted) ----
            float sacc[8][4];
            #pragma unroll
            for (int i = 0; i < 8; i++)
                #pragma unroll
                for (int j = 0; j < 4; j++) sacc[i][j] = 0.f;

            #pragma unroll
            for (int k = 0; k < 4; k++) {
                #pragma unroll
                for (int nt2 = 0; nt2 < 4; nt2++) {
                    uint32_t bh[4];
                    ldsm4(bh, ktb + aoffB + nt2 * (16 * SP * 2) + k * 32);
                    mma16816(sacc[2 * nt2],     aq[k], bh);
                    mma16816(sacc[2 * nt2 + 1], aq[k], bh + 2);
                }
            }

            // ---- softmax: p = 2^(s-4) via packed f16x2 MUFU; mask on boundary tiles ----
            uint32_t pah[4][4];
            const bool fullband = (doff >= wr * 16 - 113) && (doff <= wr * 16 + 65);
            if (!fullband) {
                #pragma unroll
                for (int nt = 0; nt < 8; nt++) {
                    int jg0 = jc + nt * 8 + 2 * qa, jg1 = jg0 + 1;
                    float s00 = ((unsigned)(jg0 - (ig0 - CTX)) <= 2u * CTX) ? sacc[nt][0] - SSHIFT : -30000.f;
                    float s01 = ((unsigned)(jg1 - (ig0 - CTX)) <= 2u * CTX) ? sacc[nt][1] - SSHIFT : -30000.f;
                    float s10 = ((unsigned)(jg0 - (ig1 - CTX)) <= 2u * CTX) ? sacc[nt][2] - SSHIFT : -30000.f;
                    float s11 = ((unsigned)(jg1 - (ig1 - CTX)) <= 2u * CTX) ? sacc[nt][3] - SSHIFT : -30000.f;
                    pah[nt >> 1][(nt & 1) * 2 + 0] = ex2_f16x2(pack_f16(s00, s01));
                    pah[nt >> 1][(nt & 1) * 2 + 1] = ex2_f16x2(pack_f16(s10, s11));
                }
            } else {
                #pragma unroll
                for (int nt = 0; nt < 8; nt++) {
                    pah[nt >> 1][(nt & 1) * 2 + 0] =
                        ex2_f16x2(pack_f16(sacc[nt][0] - SSHIFT, sacc[nt][1] - SSHIFT));
                    pah[nt >> 1][(nt & 1) * 2 + 1] =
                        ex2_f16x2(pack_f16(sacc[nt][2] - SSHIFT, sacc[nt][3] - SSHIFT));
                }
            }

            // ---- GEMM2: O(16x64) += P V; l += P * ones ----
            #pragma unroll
            for (int ks = 0; ks < 4; ks++) {
                mma16816(lacc, pah[ks], ones2);   // row sums (exact over quantized P)
                #pragma unroll
                for (int nt2 = 0; nt2 < 4; nt2++) {
                    uint32_t vh[4];
                    ldsm4t(vh, vtb + aoffV + ks * (16 * SP * 2) + nt2 * 32);
                    mma16816(oacc[2 * nt2],     pah[ks], vh);
                    mma16816(oacc[2 * nt2 + 1], pah[ks], vh + 2);
                }
            }
        }

        // ---- convert next chunk raw -> tiles(b^1) (own bytes; self-visible) ----
        if (ch < chhi) {
            CPA_WAIT0();
            const uint32_t kt = KT0 + (uint32_t)(b ^ 1) * KVTILE;
            const uint32_t vt = VT0 + (uint32_t)(b ^ 1) * KVTILE;
            #pragma unroll
            for (int it = 0; it < 4; it++) {
                int r = pr + it * 16;
                uint32_t roff = (uint32_t)(r * 64 + pc4) * 4;
                uint32_t boff = (uint32_t)(r * SP + pc4) * 2;
                float4 k4 = *(const float4*)(smem + RAWK + roff);
                *(uint2*)(smem + kt + boff) = make_uint2(pack_f16(k4.x, k4.y),
                                                         pack_f16(k4.z, k4.w));
                float4 v4 = *(const float4*)(smem + RAWV + roff);
                *(uint2*)(smem + vt + boff) = make_uint2(pack_f16(v4.x, v4.y),
                                                         pack_f16(v4.z, v4.w));
            }
        }
        __syncthreads();   // converts visible; tile(b) reads done before overwrite
    }

    // ---- epilogue: l already complete per-row in lacc (no shuffles) ----
    const float inv0 = 1.0f / lacc[0], inv1 = 1.0f / lacc[2];

    __syncthreads();   // all warps done with K/V tiles before aliasing as OB

    float* Ob = (float*)(smem + OB);
    const int r0 = wr * 16 + g, r1 = r0 + 8;
    #pragma unroll
    for (int nt = 0; nt < 8; nt++) {
        int c = nt * 8 + 2 * qa;
        *(float2*)&Ob[r0 * OPS + c] = make_float2(oacc[nt][0] * inv0, oacc[nt][1] * inv0);
        *(float2*)&Ob[r1 * OPS + c] = make_float2(oacc[nt][2] * inv1, oacc[nt][3] * inv1);
    }
    __syncthreads();

    // ---- coalesced store ----
    for (int idx = t; idx < QT * 16; idx += 256) {
        int r = idx >> 4, c4 = (idx & 15) * 4;
        float4 o4 = *(const float4*)&Ob[r * OPS + c4];
        *(float4*)&og[(size_t)(i0 + r) * DMODEL + hoff + c4] = o4;
    }
}

extern "C" void kernel_launch(void* const* d_in, const int* in_sizes, int n_in,
                              void* d_out, int out_size) {
    (void)in_sizes; (void)n_in; (void)out_size;
    const float* q = (const float*)d_in[0];
    const float* k = (const float*)d_in[1];
    const float* v = (const float*)d_in[2];
    float* o = (float*)d_out;

    cudaFuncSetAttribute(sparse_attn_mma,
                         cudaFuncAttributeMaxDynamicSharedMemorySize, SMEM_BYTES);
    dim3 grid(NSEQ / QT, HEADS);
    sparse_attn_mma<<<grid, 256, SMEM_BYTES>>>(q, k, v, o);
}

// round 15
// speedup vs baseline: 1.0947x; 1.0016x over previous
#include <cuda_runtime.h>
#include <cuda_fp16.h>
#include <cstdint>

#define NSEQ   2048
#define DMODEL 1024
#define HEADS  16
#define DH     64
#define CTX    128
#define QT     128
#define NCHUNK 6
#define SP     72            // padded smem row stride (fp16 elems) -> 144B
#define QSCALE 0.18033688011112042f   // 0.125 * log2(e): softmax = 2^s
#define SINIT  0xC400C400u   // f16x2 {-4,-4}: GEMM1 C-init = -SSHIFT (2^-4 cancels in norm)
#define KVTILE (64*SP*2)     // 9216 B per 64x64 fp16 tile

// ---- smem byte offsets ----
#define QTI  0                        // 128xSP fp16 = 18432
#define KT0  18432
#define KT1  (KT0 + KVTILE)
#define VT0  (KT1 + KVTILE)
#define VT1  (VT0 + KVTILE)
#define RAWK (VT1 + KVTILE)          // fp32 staging 64x64
#define RAWV (RAWK + 16384)
#define SMEM_BYTES (RAWV + 16384)
// epilogue alias (over K/V tiles, AFTER a full __syncthreads): 128x68 f32
#define OB   KT0
#define OPS  68

__device__ __forceinline__ uint32_t smem_u32(const void* p) {
    uint32_t a;
    asm("{ .reg .u64 t; cvta.to.shared.u64 t, %1; cvt.u32.u64 %0, t; }" : "=r"(a) : "l"(p));
    return a;
}
__device__ __forceinline__ void cpa16(uint32_t dst, const void* src) {
    asm volatile("cp.async.cg.shared.global [%0], [%1], 16;" :: "r"(dst), "l"(src));
}
#define CPA_COMMIT() asm volatile("cp.async.commit_group;" ::: "memory")
#define CPA_WAIT0()  asm volatile("cp.async.wait_group 0;" ::: "memory")

__device__ __forceinline__ void ldsm4(uint32_t* r, uint32_t a) {
    asm volatile("ldmatrix.sync.aligned.m8n8.x4.shared.b16 {%0,%1,%2,%3}, [%4];"
                 : "=r"(r[0]), "=r"(r[1]), "=r"(r[2]), "=r"(r[3]) : "r"(a));
}
__device__ __forceinline__ void ldsm4t(uint32_t* r, uint32_t a) {
    asm volatile("ldmatrix.sync.aligned.m8n8.x4.trans.shared.b16 {%0,%1,%2,%3}, [%4];"
                 : "=r"(r[0]), "=r"(r[1]), "=r"(r[2]), "=r"(r[3]) : "r"(a));
}
// fp32-accumulator fp16 MMA (GEMM2 / row sums)
__device__ __forceinline__ void mma16816(float* c, const uint32_t* a, const uint32_t* b) {
    asm volatile("mma.sync.aligned.m16n8k16.row.col.f32.f16.f16.f32 "
                 "{%0,%1,%2,%3}, {%4,%5,%6,%7}, {%8,%9}, {%0,%1,%2,%3};"
                 : "+f"(c[0]), "+f"(c[1]), "+f"(c[2]), "+f"(c[3])
                 : "r"(a[0]), "r"(a[1]), "r"(a[2]), "r"(a[3]), "r"(b[0]), "r"(b[1]));
}
// fp16-accumulator fp16 MMA (GEMM1: D packed f16x2, layout == ex2 input == GEMM2 A-frag)
__device__ __forceinline__ void mma16816h(uint32_t* c, const uint32_t* a, const uint32_t* b) {
    asm volatile("mma.sync.aligned.m16n8k16.row.col.f16.f16.f16.f16 "
                 "{%0,%1}, {%2,%3,%4,%5}, {%6,%7}, {%0,%1};"
                 : "+r"(c[0]), "+r"(c[1])
                 : "r"(a[0]), "r"(a[1]), "r"(a[2]), "r"(a[3]), "r"(b[0]), "r"(b[1]));
}
// pack two fp32 -> fp16x2 (first arg lands in low half)
__device__ __forceinline__ uint32_t pack_f16(float lo, float hi) {
    uint32_t r;
    asm("cvt.rn.f16x2.f32 %0, %1, %2;" : "=r"(r) : "f"(hi), "f"(lo));
    return r;
}
// packed 2^x on the MUFU pipe (fp16x2 in/out)
__device__ __forceinline__ uint32_t ex2_f16x2(uint32_t x) {
    uint32_t r; asm("ex2.approx.f16x2 %0, %1;" : "=r"(r) : "r"(x));
    return r;
}
__device__ __forceinline__ uint32_t mul_f16x2(uint32_t a, uint32_t b) {
    uint32_t r; asm("mul.rn.f16x2 %0, %1, %2;" : "=r"(r) : "r"(a), "r"(b));
    return r;
}

__global__ void __launch_bounds__(256, 2)
sparse_attn_mma(const float* __restrict__ qg, const float* __restrict__ kg,
                const float* __restrict__ vg, float* __restrict__ og)
{
    extern __shared__ char smem[];
    const uint32_t sb = smem_u32(smem);
    const int t    = threadIdx.x;
    const int lane = t & 31, wid = t >> 5;
    const int wr   = wid;              // row group: 16 rows, warp owns all 64 chunk cols
    const int g    = lane >> 2;        // row-in-group (and +8)
    const int qa   = lane & 3;         // col pair selector
    const int h    = blockIdx.y;
    const int i0   = blockIdx.x * QT;
    const size_t hoff = (size_t)h * DH;

    // staging coords: each thread cp.asyncs AND converts exactly its own bytes
    const int pr  = t >> 4;            // +16 per pass, 4 passes -> 64 rows
    const int pc4 = (t & 15) * 4;

    // contiguous valid chunk range: jc in [0, NSEQ-64]
    const int chlo = (i0 >= CTX) ? 0 : (CTX - i0 + 63) / 64;
    const int chhi = min(NCHUNK - 1, (NSEQ - 64 - i0 + CTX) / 64);

    // ---- prologue: prefetch first chunk ----
    {
        const int jc = i0 - CTX + chlo * 64;
        #pragma unroll
        for (int it = 0; it < 4; it++) {
            int r = pr + it * 16;
            cpa16(sb + RAWK + (uint32_t)(r * 64 + pc4) * 4,
                  &kg[(size_t)(jc + r) * DMODEL + hoff + pc4]);
            cpa16(sb + RAWV + (uint32_t)(r * 64 + pc4) * 4,
                  &vg[(size_t)(jc + r) * DMODEL + hoff + pc4]);
        }
        CPA_COMMIT();
    }

    // ---- load Q once: scale (incl. log2e), single fp16 ----
    for (int idx = t; idx < QT * 16; idx += 256) {
        int r = idx >> 4, c4 = (idx & 15) * 4;
        float4 q4 = *(const float4*)&qg[(size_t)(i0 + r) * DMODEL + hoff + c4];
        q4.x *= QSCALE; q4.y *= QSCALE; q4.z *= QSCALE; q4.w *= QSCALE;
        uint32_t boff = (uint32_t)(r * SP + c4) * 2;
        *(uint2*)(smem + QTI + boff) = make_uint2(pack_f16(q4.x, q4.y), pack_f16(q4.z, q4.w));
    }

    // ---- prologue convert: raw -> fp16 tiles (own bytes only) ----
    {
        CPA_WAIT0();
        const uint32_t kt = KT0 + (uint32_t)(chlo & 1) * KVTILE;
        const uint32_t vt = VT0 + (uint32_t)(chlo & 1) * KVTILE;
        #pragma unroll
        for (int it = 0; it < 4; it++) {
            int r = pr + it * 16;
            uint32_t roff = (uint32_t)(r * 64 + pc4) * 4;
            uint32_t boff = (uint32_t)(r * SP + pc4) * 2;
            float4 k4 = *(const float4*)(smem + RAWK + roff);
            *(uint2*)(smem + kt + boff) = make_uint2(pack_f16(k4.x, k4.y), pack_f16(k4.z, k4.w));
            float4 v4 = *(const float4*)(smem + RAWV + roff);
            *(uint2*)(smem + vt + boff) = make_uint2(pack_f16(v4.x, v4.y), pack_f16(v4.z, v4.w));
        }
    }
    __syncthreads();   // Q tile + first converts visible

    // ldmatrix per-lane byte offsets
    const int l = lane;
    const uint32_t aoffA = (uint32_t)(((wr * 16 + (l & 15)) * SP + (l >> 4) * 8) * 2);
    const uint32_t aoffB = (uint32_t)((((l & 7) + ((l >> 4) & 1) * 8) * SP
                                      + ((l >> 3) & 1) * 8) * 2);
    const uint32_t aoffV = (uint32_t)((((l & 7) + ((l >> 3) & 1) * 8) * SP
                                      + ((l >> 4) & 1) * 8) * 2);

    // ---- hoist Q fragments into registers (chunk-invariant) ----
    uint32_t aq[4][4];
    #pragma unroll
    for (int k = 0; k < 4; k++)
        ldsm4(aq[k], sb + QTI + aoffA + k * 32);

    float oacc[8][4];
    #pragma unroll
    for (int i = 0; i < 8; i++)
        #pragma unroll
        for (int j = 0; j < 4; j++) oacc[i][j] = 0.f;
    float lacc[4] = {0.f, 0.f, 0.f, 0.f};   // row sums via ones-MMA
    const uint32_t ones2[2] = {0x3C003C00u, 0x3C003C00u};  // fp16 1.0 x2

    const int ig0 = i0 + wr * 16 + g, ig1 = ig0 + 8;

    for (int ch = chlo; ch <= chhi; ch++) {
        const int b  = ch & 1;
        const int jc = i0 - CTX + ch * 64;

        // ---- prefetch chunk ch+1 (overlaps compute) ----
        if (ch < chhi) {
            const int jn = jc + 64;
            #pragma unroll
            for (int it = 0; it < 4; it++) {
                int r = pr + it * 16;
                cpa16(sb + RAWK + (uint32_t)(r * 64 + pc4) * 4,
                      &kg[(size_t)(jn + r) * DMODEL + hoff + pc4]);
                cpa16(sb + RAWV + (uint32_t)(r * 64 + pc4) * 4,
                      &vg[(size_t)(jn + r) * DMODEL + hoff + pc4]);
            }
            CPA_COMMIT();
        }

        // ---- warp-tile band intersection: keys [jc,jc+64) vs rows [wr*16, wr*16+16) ----
        const int doff = jc - i0;
        const bool active = (doff + 63 >= wr * 16 - CTX) && (doff <= wr * 16 + 15 + CTX);
        if (active) {
            const uint32_t ktb = sb + KT0 + (uint32_t)b * KVTILE;
            const uint32_t vtb = sb + VT0 + (uint32_t)b * KVTILE;

            // ---- GEMM1: S(16x64) = Q K^T - 4, fp16 accumulate (packed f16x2 D) ----
            uint32_t sp2[8][2];
            #pragma unroll
            for (int i = 0; i < 8; i++) { sp2[i][0] = SINIT; sp2[i][1] = SINIT; }

            #pragma unroll
            for (int k = 0; k < 4; k++) {
                #pragma unroll
                for (int nt2 = 0; nt2 < 4; nt2++) {
                    uint32_t bh[4];
                    ldsm4(bh, ktb + aoffB + nt2 * (16 * SP * 2) + k * 32);
                    mma16816h(sp2[2 * nt2],     aq[k], bh);
                    mma16816h(sp2[2 * nt2 + 1], aq[k], bh + 2);
                }
            }

            // ---- softmax: p = 2^(s-4) in place via packed MUFU ----
            #pragma unroll
            for (int nt = 0; nt < 8; nt++) {
                sp2[nt][0] = ex2_f16x2(sp2[nt][0]);
                sp2[nt][1] = ex2_f16x2(sp2[nt][1]);
            }
            // band mask (exact 0) only on tiles straddling the band edge
            const bool fullband = (doff >= wr * 16 - 113) && (doff <= wr * 16 + 65);
            if (!fullband) {
                #pragma unroll
                for (int nt = 0; nt < 8; nt++) {
                    int jg0 = jc + nt * 8 + 2 * qa, jg1 = jg0 + 1;
                    uint32_t m0 = (((unsigned)(jg0 - (ig0 - CTX)) <= 2u * CTX) ? 0x3C00u : 0u)
                                | (((unsigned)(jg1 - (ig0 - CTX)) <= 2u * CTX) ? 0x3C000000u : 0u);
                    uint32_t m1 = (((unsigned)(jg0 - (ig1 - CTX)) <= 2u * CTX) ? 0x3C00u : 0u)
                                | (((unsigned)(jg1 - (ig1 - CTX)) <= 2u * CTX) ? 0x3C000000u : 0u);
                    sp2[nt][0] = mul_f16x2(sp2[nt][0], m0);
                    sp2[nt][1] = mul_f16x2(sp2[nt][1], m1);
                }
            }

            // ---- GEMM2: O(16x64) += P V; l += P * ones ----
            #pragma unroll
            for (int ks = 0; ks < 4; ks++) {
                const uint32_t* pa = &sp2[2 * ks][0];   // 4 contiguous regs = A-frag
                mma16816(lacc, pa, ones2);              // row sums over quantized P
                #pragma unroll
                for (int nt2 = 0; nt2 < 4; nt2++) {
                    uint32_t vh[4];
                    ldsm4t(vh, vtb + aoffV + ks * (16 * SP * 2) + nt2 * 32);
                    mma16816(oacc[2 * nt2],     pa, vh);
                    mma16816(oacc[2 * nt2 + 1], pa, vh + 2);
                }
            }
        }

        // ---- convert next chunk raw -> tiles(b^1) (own bytes; self-visible) ----
        if (ch < chhi) {
            CPA_WAIT0();
            const uint32_t kt = KT0 + (uint32_t)(b ^ 1) * KVTILE;
            const uint32_t vt = VT0 + (uint32_t)(b ^ 1) * KVTILE;
            #pragma unroll
            for (int it = 0; it < 4; it++) {
                int r = pr + it * 16;
                uint32_t roff = (uint32_t)(r * 64 + pc4) * 4;
                uint32_t boff = (uint32_t)(r * SP + pc4) * 2;
                float4 k4 = *(const float4*)(smem + RAWK + roff);
                *(uint2*)(smem + kt + boff) = make_uint2(pack_f16(k4.x, k4.y),
                                                         pack_f16(k4.z, k4.w));
                float4 v4 = *(const float4*)(smem + RAWV + roff);
                *(uint2*)(smem + vt + boff) = make_uint2(pack_f16(v4.x, v4.y),
                                                         pack_f16(v4.z, v4.w));
            }
        }
        __syncthreads();   // converts visible; tile(b) reads done before overwrite
    }

    // ---- epilogue: l already complete per-row in lacc (no shuffles) ----
    const float inv0 = 1.0f / lacc[0], inv1 = 1.0f / lacc[2];

    __syncthreads();   // all warps done with K/V tiles before aliasing as OB

    float* Ob = (float*)(smem + OB);
    const int r0 = wr * 16 + g, r1 = r0 + 8;
    #pragma unroll
    for (int nt = 0; nt < 8; nt++) {
        int c = nt * 8 + 2 * qa;
        *(float2*)&Ob[r0 * OPS + c] = make_float2(oacc[nt][0] * inv0, oacc[nt][1] * inv0);
        *(float2*)&Ob[r1 * OPS + c] = make_float2(oacc[nt][2] * inv1, oacc[nt][3] * inv1);
    }
    __syncthreads();

    // ---- coalesced store ----
    for (int idx = t; idx < QT * 16; idx += 256) {
        int r = idx >> 4, c4 = (idx & 15) * 4;
        float4 o4 = *(const float4*)&Ob[r * OPS + c4];
        *(float4*)&og[(size_t)(i0 + r) * DMODEL + hoff + c4] = o4;
    }
}

extern "C" void kernel_launch(void* const* d_in, const int* in_sizes, int n_in,
                              void* d_out, int out_size) {
    (void)in_sizes; (void)n_in; (void)out_size;
    const float* q = (const float*)d_in[0];
    const float* k = (const float*)d_in[1];
    const float* v = (const float*)d_in[2];
    float* o = (float*)d_out;

    cudaFuncSetAttribute(sparse_attn_mma,
                         cudaFuncAttributeMaxDynamicSharedMemorySize, SMEM_BYTES);
    dim3 grid(NSEQ / QT, HEADS);
    sparse_attn_mma<<<grid, 256, SMEM_BYTES>>>(q, k, v, o);
}